// round 6
// baseline (speedup 1.0000x reference)
#include <cuda_runtime.h>
#include <cstdint>

#define NN    50000
#define NE    800000
#define HD    64
#define MH    128
#define MHP   132    // padded stride (mod 32 == 4 -> conflict-free A-frags)
#define ET    64     // edge tile
#define PCS   260    // sPcat row stride (floats)

// scratch
__device__ float g_agg[(size_t)NN * HD];
__device__ float g_Pcat[(size_t)NN * 256];   // [ h@W_src | h@W_dst ]

__device__ __forceinline__ float f2tf(float f) {
    uint32_t u;
    asm("cvt.rna.tf32.f32 %0, %1;" : "=r"(u) : "f"(f));
    return __uint_as_float(u);
}

__device__ __forceinline__ void mma_tf32(float c[4], const uint32_t a[4],
                                         uint32_t b0, uint32_t b1) {
    asm volatile(
        "mma.sync.aligned.m16n8k8.row.col.f32.tf32.tf32.f32 "
        "{%0,%1,%2,%3},{%4,%5,%6,%7},{%8,%9},{%0,%1,%2,%3};"
        : "+f"(c[0]), "+f"(c[1]), "+f"(c[2]), "+f"(c[3])
        : "r"(a[0]), "r"(a[1]), "r"(a[2]), "r"(a[3]), "r"(b0), "r"(b1));
}

__device__ __forceinline__ void cp16(uint32_t smem_addr, const void* gptr) {
    asm volatile("cp.async.ca.shared.global [%0], [%1], 16;"
                 :: "r"(smem_addr), "l"(gptr) : "memory");
}

// ---------------------------------------------------------------------------
// prep: Pcat[n, 0:256] = h[n] @ [W_src | W_dst]; also zeroes g_agg rows.
// ---------------------------------------------------------------------------
__global__ __launch_bounds__(512, 1)
void prep_kernel(const float* __restrict__ h, const float* __restrict__ eW1)
{
    extern __shared__ float sm[];
    float* sW = sm;             // 64 x 256, col-swizzled
    float* sA = sW + 64 * 256;  // 128 x 68

    const int tid  = threadIdx.x;
    const int lane = tid & 31;
    const int w    = tid >> 5;
    const int lq   = lane >> 2;
    const int lr   = lane & 3;
    const int n0g  = blockIdx.x * 128;

    for (int i = tid; i < 128 * 16; i += 512) {
        int r = i >> 4, c4 = i & 15;
        int node = n0g + r;
        if (node < NN)
            reinterpret_cast<float4*>(g_agg)[(size_t)node * 16 + c4] =
                make_float4(0.f, 0.f, 0.f, 0.f);
    }

    for (int i = tid; i < 64 * 256; i += 512) {
        int k = i >> 8, c = i & 255;
        float v = (c < MH) ? eW1[k * MH + c] : eW1[(64 + k) * MH + (c - MH)];
        sW[k * 256 + (c ^ ((k & 3) << 3))] = f2tf(v);
    }
    for (int i = tid; i < 128 * 64; i += 512) {
        int r = i >> 6, c = i & 63;
        int node = min(n0g + r, NN - 1);
        sA[r * 68 + c] = f2tf(h[(size_t)node * HD + c]);
    }
    __syncthreads();

    const int mh = w >> 2, nc = w & 3;

    float acc[2][8][4];
    #pragma unroll
    for (int i = 0; i < 2; i++)
        #pragma unroll
        for (int j = 0; j < 8; j++)
            #pragma unroll
            for (int q = 0; q < 4; q++) acc[i][j][q] = 0.f;

    for (int k = 0; k < 64; k += 8) {
        uint32_t a[2][4];
        #pragma unroll
        for (int i = 0; i < 2; i++) {
            int row = mh * 32 + 16 * i + lq;
            a[i][0] = __float_as_uint(sA[row * 68 + k + lr]);
            a[i][1] = __float_as_uint(sA[(row + 8) * 68 + k + lr]);
            a[i][2] = __float_as_uint(sA[row * 68 + k + 4 + lr]);
            a[i][3] = __float_as_uint(sA[(row + 8) * 68 + k + 4 + lr]);
        }
        #pragma unroll
        for (int j = 0; j < 8; j++) {
            int n0 = nc * 64 + 8 * j;
            int cs = (n0 + lq) ^ (lr << 3);
            uint32_t b0 = __float_as_uint(sW[(k + lr) * 256 + cs]);
            uint32_t b1 = __float_as_uint(sW[(k + 4 + lr) * 256 + cs]);
            mma_tf32(acc[0][j], a[0], b0, b1);
            mma_tf32(acc[1][j], a[1], b0, b1);
        }
    }

    #pragma unroll
    for (int i = 0; i < 2; i++) {
        int r0 = mh * 32 + 16 * i + lq;
        int g0 = n0g + r0, g1 = g0 + 8;
        #pragma unroll
        for (int j = 0; j < 8; j++) {
            int col = nc * 64 + 8 * j + 2 * lr;
            if (g0 < NN)
                *(float2*)&g_Pcat[(size_t)g0 * 256 + col] =
                    make_float2(acc[i][j][0], acc[i][j][1]);
            if (g1 < NN)
                *(float2*)&g_Pcat[(size_t)g1 * 256 + col] =
                    make_float2(acc[i][j][2], acc[i][j][3]);
        }
    }
}

// ---------------------------------------------------------------------------
// Edge kernel v3: cp.async double-buffered Pcat staging.
// 512 threads, 1 CTA/SM, ET=64 edges/tile.
//   Hd = relu( ea@W_ea + PcatS[src half] + PcatS[dst half] + b1 )
//   M  = Hd @ eW2 + eb2  ->  red.global.add.v2 into g_agg[dst]
// ---------------------------------------------------------------------------
__global__ __launch_bounds__(512, 1)
void edge_kernel(const int* __restrict__ ei,
                 const float* __restrict__ ea,
                 const float* __restrict__ eW1, const float* __restrict__ eb1,
                 const float* __restrict__ eW2, const float* __restrict__ eb2)
{
    extern __shared__ float sm[];
    float* sWea = sm;                     // 8 x 128, col-swizzled
    float* sW2  = sWea + 8 * MH;          // 128 x 64, col-swizzled
    float* sH   = sW2 + MH * HD;          // 64 x 132
    float* sPc0 = sH + ET * MHP;          // 64 x 260 (buffer 0)
    float* sPc1 = sPc0 + ET * PCS;        // 64 x 260 (buffer 1)
    float* sEA0 = sPc1 + ET * PCS;        // 64 x 12
    float* sEA1 = sEA0 + ET * 12;         // 64 x 12
    int*   sIdx0 = (int*)(sEA1 + ET * 12);  // src[64] | dst[64]
    int*   sIdx1 = sIdx0 + 2 * ET;

    const int tid  = threadIdx.x;
    const int lane = tid & 31;
    const int w    = tid >> 5;
    const int lq   = lane >> 2;
    const int lr   = lane & 3;
    const int mw   = w >> 3;   // 0..1 -> m32
    const int nw   = w & 7;    // 0..7 -> n16 (phase1) / n8 (phase2)

    for (int i = tid; i < 8 * MH; i += 512) {
        int k = i >> 7, c = i & 127;
        sWea[k * MH + (c ^ ((k & 3) << 3))] = f2tf(eW1[(2 * HD + k) * MH + c]);
    }
    for (int i = tid; i < MH * HD; i += 512) {
        int r = i >> 6, n = i & 63;
        sW2[r * HD + (n ^ ((r & 3) << 3))] = f2tf(eW2[i]);
    }

    float2 b1p[2], b2p;
    #pragma unroll
    for (int j = 0; j < 2; j++)
        b1p[j] = *(const float2*)&eb1[nw * 16 + 8 * j + 2 * lr];
    b2p = *(const float2*)&eb2[nw * 8 + 2 * lr];

    const int numTiles = NE / ET;        // 12500
    const int G = gridDim.x;

    // ---- prologue: tile t0 ----
    int t = blockIdx.x;
    int pS = 0, pD = 0; float pEA = 0.f;
    if (t < numTiles) {
        const int e0 = t * ET;
        if (tid < ET) { pS = ei[e0 + tid]; pD = ei[NE + e0 + tid]; }
        pEA = ea[(size_t)e0 * 8 + tid];
    }
    // commit tile t into buffer 0
    if (t < numTiles) {
        if (tid < ET) {
            sIdx0[tid]      = min(max(pS, 0), NN - 1);
            sIdx0[ET + tid] = min(max(pD, 0), NN - 1);
        }
        sEA0[(tid >> 3) * 12 + (tid & 7)] = f2tf(pEA);
    }
    __syncthreads();
    // issue cp.async for tile t into sPc0
    if (t < numTiles) {
        #pragma unroll
        for (int v = 0; v < 8; v++) {
            int id  = v * 512 + tid;
            int row = id >> 6;
            int seg = id & 63;
            int node = (seg < 32) ? sIdx0[row] : sIdx0[ET + row];
            const void* gp = &g_Pcat[(size_t)node * 256 + seg * 4];
            uint32_t sa = (uint32_t)__cvta_generic_to_shared(&sPc0[row * PCS + seg * 4]);
            cp16(sa, gp);
        }
    }
    asm volatile("cp.async.commit_group;" ::: "memory");
    // prefetch regs for t+G
    {
        int tn = t + G;
        if (tn < numTiles) {
            const int en = tn * ET;
            if (tid < ET) { pS = ei[en + tid]; pD = ei[NE + en + tid]; }
            pEA = ea[(size_t)en * 8 + tid];
        }
    }

    int cur = 0;
    for (; t < numTiles; t += G) {
        float* sPcC = cur ? sPc1 : sPc0;
        float* sPcN = cur ? sPc0 : sPc1;
        float* sEAC = cur ? sEA1 : sEA0;
        float* sEAN = cur ? sEA0 : sEA1;
        int*   sIdC = cur ? sIdx1 : sIdx0;
        int*   sIdN = cur ? sIdx0 : sIdx1;

        __syncthreads();   // (A) prev iter done with the "next" buffers

        // commit regs (tile t+G) into next buffers
        if (t + G < numTiles) {
            if (tid < ET) {
                sIdN[tid]      = min(max(pS, 0), NN - 1);
                sIdN[ET + tid] = min(max(pD, 0), NN - 1);
            }
            sEAN[(tid >> 3) * 12 + (tid & 7)] = f2tf(pEA);
        }
        __syncthreads();   // (B) sIdN visible

        // issue cp.async for tile t+G
        if (t + G < numTiles) {
            #pragma unroll
            for (int v = 0; v < 8; v++) {
                int id  = v * 512 + tid;
                int row = id >> 6;
                int seg = id & 63;
                int node = (seg < 32) ? sIdN[row] : sIdN[ET + row];
                const void* gp = &g_Pcat[(size_t)node * 256 + seg * 4];
                uint32_t sa = (uint32_t)__cvta_generic_to_shared(&sPcN[row * PCS + seg * 4]);
                cp16(sa, gp);
            }
        }
        asm volatile("cp.async.commit_group;" ::: "memory");

        // prefetch regs for t+2G
        if (t + 2 * G < numTiles) {
            const int en = (t + 2 * G) * ET;
            if (tid < ET) { pS = ei[en + tid]; pD = ei[NE + en + tid]; }
            pEA = ea[(size_t)en * 8 + tid];
        }

        asm volatile("cp.async.wait_group 1;" ::: "memory");  // tile t staged
        __syncthreads();   // (C)

        // ---- phase 1: ea@Wea (K=8) + staged Pcat + bias, relu -> sH ----
        float c1[2][2][4];
        #pragma unroll
        for (int i = 0; i < 2; i++)
            #pragma unroll
            for (int j = 0; j < 2; j++)
                #pragma unroll
                for (int q = 0; q < 4; q++) c1[i][j][q] = 0.f;

        {
            uint32_t a[2][4];
            #pragma unroll
            for (int i = 0; i < 2; i++) {
                int row = mw * 32 + 16 * i + lq;
                a[i][0] = __float_as_uint(sEAC[row * 12 + lr]);
                a[i][1] = __float_as_uint(sEAC[(row + 8) * 12 + lr]);
                a[i][2] = __float_as_uint(sEAC[row * 12 + 4 + lr]);
                a[i][3] = __float_as_uint(sEAC[(row + 8) * 12 + 4 + lr]);
            }
            #pragma unroll
            for (int j = 0; j < 2; j++) {
                int n0 = nw * 16 + 8 * j;
                int cs = (n0 + lq) ^ (lr << 3);
                uint32_t b0 = __float_as_uint(sWea[lr * MH + cs]);
                uint32_t b1 = __float_as_uint(sWea[(4 + lr) * MH + cs]);
                mma_tf32(c1[0][j], a[0], b0, b1);
                mma_tf32(c1[1][j], a[1], b0, b1);
            }
        }

        #pragma unroll
        for (int i = 0; i < 2; i++) {
            int r0 = mw * 32 + 16 * i + lq;
            int r1 = r0 + 8;
            #pragma unroll
            for (int j = 0; j < 2; j++) {
                int col = nw * 16 + 8 * j + 2 * lr;
                float2 s0 = *(const float2*)&sPcC[r0 * PCS + col];
                float2 d0 = *(const float2*)&sPcC[r0 * PCS + 128 + col];
                float2 s1 = *(const float2*)&sPcC[r1 * PCS + col];
                float2 d1 = *(const float2*)&sPcC[r1 * PCS + 128 + col];
                uint2 v0, v1;
                v0.x = __float_as_uint(f2tf(fmaxf(c1[i][j][0] + s0.x + d0.x + b1p[j].x, 0.f)));
                v0.y = __float_as_uint(f2tf(fmaxf(c1[i][j][1] + s0.y + d0.y + b1p[j].y, 0.f)));
                v1.x = __float_as_uint(f2tf(fmaxf(c1[i][j][2] + s1.x + d1.x + b1p[j].x, 0.f)));
                v1.y = __float_as_uint(f2tf(fmaxf(c1[i][j][3] + s1.y + d1.y + b1p[j].y, 0.f)));
                *(uint2*)&sH[r0 * MHP + col] = v0;
                *(uint2*)&sH[r1 * MHP + col] = v1;
            }
        }
        __syncthreads();   // (D) sH ready

        // ---- phase 2: [64,128] @ [128,64] ----
        float c2[2][4];
        #pragma unroll
        for (int i = 0; i < 2; i++)
            #pragma unroll
            for (int q = 0; q < 4; q++) c2[i][q] = 0.f;

        const int n0 = nw * 8;
        for (int k = 0; k < MH; k += 8) {
            uint32_t a[2][4];
            #pragma unroll
            for (int i = 0; i < 2; i++) {
                int row = mw * 32 + 16 * i + lq;
                a[i][0] = __float_as_uint(sH[row * MHP + k + lr]);
                a[i][1] = __float_as_uint(sH[(row + 8) * MHP + k + lr]);
                a[i][2] = __float_as_uint(sH[row * MHP + k + 4 + lr]);
                a[i][3] = __float_as_uint(sH[(row + 8) * MHP + k + 4 + lr]);
            }
            int cs = (n0 + lq) ^ (lr << 3);
            uint32_t b0 = __float_as_uint(sW2[(k + lr) * HD + cs]);
            uint32_t b1 = __float_as_uint(sW2[(k + 4 + lr) * HD + cs]);
            mma_tf32(c2[0], a[0], b0, b1);
            mma_tf32(c2[1], a[1], b0, b1);
        }

        // scatter-add (bias folded)
        #pragma unroll
        for (int i = 0; i < 2; i++) {
            int r0 = mw * 32 + 16 * i + lq;
            int r1 = r0 + 8;
            int d0 = sIdC[ET + r0], d1 = sIdC[ET + r1];
            int col = n0 + 2 * lr;
            float u0 = c2[i][0] + b2p.x;
            float u1 = c2[i][1] + b2p.y;
            float u2 = c2[i][2] + b2p.x;
            float u3 = c2[i][3] + b2p.y;
            float* p0 = g_agg + (size_t)d0 * HD + col;
            float* p1 = g_agg + (size_t)d1 * HD + col;
            asm volatile("red.global.add.v2.f32 [%0], {%1, %2};"
                         :: "l"(p0), "f"(u0), "f"(u1) : "memory");
            asm volatile("red.global.add.v2.f32 [%0], {%1, %2};"
                         :: "l"(p1), "f"(u2), "f"(u3) : "memory");
        }

        cur ^= 1;
    }
}

// ---------------------------------------------------------------------------
// Node kernel (unchanged): tf32 MMA, 64 nodes/tile, 256 threads
// ---------------------------------------------------------------------------
#define TILE 64
__global__ __launch_bounds__(256, 1)
void node_kernel(const float* __restrict__ h,
                 const float* __restrict__ nW1, const float* __restrict__ nb1,
                 const float* __restrict__ nW2, const float* __restrict__ nb2,
                 const float* __restrict__ lg,  const float* __restrict__ lb,
                 float* __restrict__ out)
{
    extern __shared__ float sm[];
    float* sW1 = sm;
    float* sW2 = sW1 + MH * MH;
    float* sU  = sW2 + MH * HD;
    float* sH  = sU  + TILE * MHP;
    float* sO  = sH  + TILE * MHP;
    float* sB1 = sO  + TILE * 65;
    float* sB2 = sB1 + MH;
    float* sG  = sB2 + HD;
    float* sB  = sG  + HD;
    float* sMu = sB  + HD;
    float* sRs = sMu + TILE;

    const int tid  = threadIdx.x;
    const int lane = tid & 31;
    const int w    = tid >> 5;
    const int lq   = lane >> 2;
    const int lr   = lane & 3;

    for (int i = tid; i < MH * MH; i += 256) {
        int r = i >> 7, n = i & 127;
        sW1[r * MH + (n ^ ((r & 3) << 3))] = f2tf(nW1[i]);
    }
    for (int i = tid; i < MH * HD; i += 256) {
        int r = i >> 6, n = i & 63;
        sW2[r * HD + (n ^ ((r & 3) << 3))] = f2tf(nW2[i]);
    }
    for (int i = tid; i < MH; i += 256) sB1[i] = nb1[i];
    if (tid < HD) { sB2[tid] = nb2[tid]; sG[tid] = lg[tid]; sB[tid] = lb[tid]; }
    __syncthreads();

    const int mh = w >> 2, nq = w & 3;
    const int mq = w & 3,  nh = w >> 2;

    float2 b1p[4], b2p[4];
    #pragma unroll
    for (int j = 0; j < 4; j++) {
        b1p[j] = *(const float2*)&sB1[nq * 32 + 8 * j + 2 * lr];
        b2p[j] = *(const float2*)&sB2[nh * 32 + 8 * j + 2 * lr];
    }

    const int numTiles = (NN + TILE - 1) / TILE;
    for (int tile = blockIdx.x; tile < numTiles; tile += gridDim.x) {
        const int n0g = tile * TILE;
        __syncthreads();

        for (int i = tid; i < TILE * MH; i += 256) {
            int r = i >> 7;
            int k = i & 127;
            int node = min(n0g + r, NN - 1);
            float v = (k < HD) ? h[(size_t)node * HD + k]
                               : g_agg[(size_t)node * HD + (k - HD)];
            sU[r * MHP + k] = f2tf(v);
        }
        __syncthreads();

        float c1[2][4][4];
        #pragma unroll
        for (int i = 0; i < 2; i++)
            #pragma unroll
            for (int j = 0; j < 4; j++)
                #pragma unroll
                for (int q = 0; q < 4; q++) c1[i][j][q] = 0.f;

        for (int k = 0; k < MH; k += 8) {
            uint32_t a[2][4];
            #pragma unroll
            for (int i = 0; i < 2; i++) {
                int row = mh * 32 + 16 * i + lq;
                a[i][0] = __float_as_uint(sU[row * MHP + k + lr]);
                a[i][1] = __float_as_uint(sU[(row + 8) * MHP + k + lr]);
                a[i][2] = __float_as_uint(sU[row * MHP + k + 4 + lr]);
                a[i][3] = __float_as_uint(sU[(row + 8) * MHP + k + 4 + lr]);
            }
            #pragma unroll
            for (int j = 0; j < 4; j++) {
                int n0 = nq * 32 + 8 * j;
                int cs = (n0 + lq) ^ (lr << 3);
                uint32_t b0 = __float_as_uint(sW1[(k + lr) * MH + cs]);
                uint32_t b1 = __float_as_uint(sW1[(k + 4 + lr) * MH + cs]);
                mma_tf32(c1[0][j], a[0], b0, b1);
                mma_tf32(c1[1][j], a[1], b0, b1);
            }
        }

        #pragma unroll
        for (int i = 0; i < 2; i++) {
            #pragma unroll
            for (int j = 0; j < 4; j++) {
                int row = mh * 32 + 16 * i + lq;
                int col = nq * 32 + 8 * j + 2 * lr;
                uint2 v0, v1;
                v0.x = __float_as_uint(f2tf(fmaxf(c1[i][j][0] + b1p[j].x, 0.f)));
                v0.y = __float_as_uint(f2tf(fmaxf(c1[i][j][1] + b1p[j].y, 0.f)));
                v1.x = __float_as_uint(f2tf(fmaxf(c1[i][j][2] + b1p[j].x, 0.f)));
                v1.y = __float_as_uint(f2tf(fmaxf(c1[i][j][3] + b1p[j].y, 0.f)));
                *(uint2*)&sH[row * MHP + col]       = v0;
                *(uint2*)&sH[(row + 8) * MHP + col] = v1;
            }
        }
        __syncthreads();

        float c2[4][4];
        #pragma unroll
        for (int j = 0; j < 4; j++)
            #pragma unroll
            for (int q = 0; q < 4; q++) c2[j][q] = 0.f;

        const int m0 = mq * 16;
        for (int k = 0; k < MH; k += 8) {
            uint32_t a[4];
            int row = m0 + lq;
            a[0] = __float_as_uint(sH[row * MHP + k + lr]);
            a[1] = __float_as_uint(sH[(row + 8) * MHP + k + lr]);
            a[2] = __float_as_uint(sH[row * MHP + k + 4 + lr]);
            a[3] = __float_as_uint(sH[(row + 8) * MHP + k + 4 + lr]);
            #pragma unroll
            for (int j = 0; j < 4; j++) {
                int n0 = nh * 32 + 8 * j;
                int cs = (n0 + lq) ^ (lr << 3);
                uint32_t b0 = __float_as_uint(sW2[(k + lr) * HD + cs]);
                uint32_t b1 = __float_as_uint(sW2[(k + 4 + lr) * HD + cs]);
                mma_tf32(c2[j], a, b0, b1);
            }
        }

        {
            int r0 = m0 + lq;
            int r1 = r0 + 8;
            int g0 = n0g + r0, g1 = n0g + r1;
            #pragma unroll
            for (int j = 0; j < 4; j++) {
                int col = nh * 32 + 8 * j + 2 * lr;
                if (g0 < NN) {
                    float2 hv = *(const float2*)&h[(size_t)g0 * HD + col];
                    sO[r0 * 65 + col]     = c2[j][0] + b2p[j].x + hv.x;
                    sO[r0 * 65 + col + 1] = c2[j][1] + b2p[j].y + hv.y;
                }
                if (g1 < NN) {
                    float2 hv = *(const float2*)&h[(size_t)g1 * HD + col];
                    sO[r1 * 65 + col]     = c2[j][2] + b2p[j].x + hv.x;
                    sO[r1 * 65 + col + 1] = c2[j][3] + b2p[j].y + hv.y;
                }
            }
        }
        __syncthreads();

        if (tid < TILE) {
            float s = 0.f, s2 = 0.f;
            #pragma unroll 8
            for (int c = 0; c < HD; c++) {
                float v = sO[tid * 65 + c];
                s += v;
                s2 = fmaf(v, v, s2);
            }
            float mu  = s * (1.f / HD);
            float var = fmaxf(s2 * (1.f / HD) - mu * mu, 0.f);
            sMu[tid] = mu;
            sRs[tid] = rsqrtf(var + 1e-5f);
        }
        __syncthreads();

        for (int i = tid; i < TILE * HD; i += 256) {
            int r = i >> 6;
            int c = i & 63;
            int node = n0g + r;
            if (node < NN)
                out[(size_t)node * HD + c] =
                    (sO[r * 65 + c] - sMu[r]) * sRs[r] * sG[c] + sB[c];
        }
    }
}

// ---------------------------------------------------------------------------
extern "C" void kernel_launch(void* const* d_in, const int* in_sizes, int n_in,
                              void* d_out, int out_size)
{
    const float* h   = (const float*)d_in[0];
    const int*   ei  = (const int*)d_in[1];     // int32 (JAX default downcast)
    const float* ea  = (const float*)d_in[2];
    const float* eW1 = (const float*)d_in[3];
    const float* eb1 = (const float*)d_in[4];
    const float* eW2 = (const float*)d_in[5];
    const float* eb2 = (const float*)d_in[6];
    const float* nW1 = (const float*)d_in[7];
    const float* nb1 = (const float*)d_in[8];
    const float* nW2 = (const float*)d_in[9];
    const float* nb2 = (const float*)d_in[10];
    const float* lg  = (const float*)d_in[11];
    const float* lb  = (const float*)d_in[12];
    float*       out = (float*)d_out;

    const int smem_prep = (64 * 256 + 128 * 68) * 4;
    const int smem_edge = (8 * MH + MH * HD + ET * MHP + 2 * ET * PCS
                           + 2 * ET * 12) * 4 + 4 * ET * 4;
    const int smem_node = (MH * MH + MH * HD + 2 * TILE * MHP + TILE * 65
                           + MH + 5 * HD + TILE) * 4;

    cudaFuncSetAttribute(prep_kernel, cudaFuncAttributeMaxDynamicSharedMemorySize, smem_prep);
    cudaFuncSetAttribute(edge_kernel, cudaFuncAttributeMaxDynamicSharedMemorySize, smem_edge);
    cudaFuncSetAttribute(node_kernel, cudaFuncAttributeMaxDynamicSharedMemorySize, smem_node);

    prep_kernel<<<(NN + 127) / 128, 512, smem_prep>>>(h, eW1);
    edge_kernel<<<148, 512, smem_edge>>>(ei, ea, eW1, eb1, eW2, eb2);
    node_kernel<<<148, 256, smem_node>>>(h, nW1, nb1, nW2, nb2, lg, lb, out);
}

// round 7
// speedup vs baseline: 1.2044x; 1.2044x over previous
#include <cuda_runtime.h>
#include <cstdint>

#define NN    50000
#define NE    800000
#define HD    64
#define MH    128
#define MHP   132    // padded stride (mod 32 == 4 -> conflict-free A-frags)
#define ET    64     // edge tile

// scratch
__device__ float g_agg[(size_t)NN * HD];
__device__ float g_Pcat[(size_t)NN * 256];   // [ h@W_src | h@W_dst ]

__device__ __forceinline__ float f2tf(float f) {
    uint32_t u;
    asm("cvt.rna.tf32.f32 %0, %1;" : "=r"(u) : "f"(f));
    return __uint_as_float(u);
}

__device__ __forceinline__ void mma_tf32(float c[4], const uint32_t a[4],
                                         uint32_t b0, uint32_t b1) {
    asm volatile(
        "mma.sync.aligned.m16n8k8.row.col.f32.tf32.tf32.f32 "
        "{%0,%1,%2,%3},{%4,%5,%6,%7},{%8,%9},{%0,%1,%2,%3};"
        : "+f"(c[0]), "+f"(c[1]), "+f"(c[2]), "+f"(c[3])
        : "r"(a[0]), "r"(a[1]), "r"(a[2]), "r"(a[3]), "r"(b0), "r"(b1));
}

// ---------------------------------------------------------------------------
// prep: Pcat[n, 0:256] = h[n] @ [W_src | W_dst]; also zeroes g_agg rows.
// ---------------------------------------------------------------------------
__global__ __launch_bounds__(512, 1)
void prep_kernel(const float* __restrict__ h, const float* __restrict__ eW1)
{
    extern __shared__ float sm[];
    float* sW = sm;             // 64 x 256, col-swizzled
    float* sA = sW + 64 * 256;  // 128 x 68

    const int tid  = threadIdx.x;
    const int lane = tid & 31;
    const int w    = tid >> 5;
    const int lq   = lane >> 2;
    const int lr   = lane & 3;
    const int n0g  = blockIdx.x * 128;

    for (int i = tid; i < 128 * 16; i += 512) {
        int r = i >> 4, c4 = i & 15;
        int node = n0g + r;
        if (node < NN)
            reinterpret_cast<float4*>(g_agg)[(size_t)node * 16 + c4] =
                make_float4(0.f, 0.f, 0.f, 0.f);
    }

    for (int i = tid; i < 64 * 256; i += 512) {
        int k = i >> 8, c = i & 255;
        float v = (c < MH) ? eW1[k * MH + c] : eW1[(64 + k) * MH + (c - MH)];
        sW[k * 256 + (c ^ ((k & 3) << 3))] = f2tf(v);
    }
    for (int i = tid; i < 128 * 64; i += 512) {
        int r = i >> 6, c = i & 63;
        int node = min(n0g + r, NN - 1);
        sA[r * 68 + c] = f2tf(h[(size_t)node * HD + c]);
    }
    __syncthreads();

    const int mh = w >> 2, nc = w & 3;

    float acc[2][8][4];
    #pragma unroll
    for (int i = 0; i < 2; i++)
        #pragma unroll
        for (int j = 0; j < 8; j++)
            #pragma unroll
            for (int q = 0; q < 4; q++) acc[i][j][q] = 0.f;

    for (int k = 0; k < 64; k += 8) {
        uint32_t a[2][4];
        #pragma unroll
        for (int i = 0; i < 2; i++) {
            int row = mh * 32 + 16 * i + lq;
            a[i][0] = __float_as_uint(sA[row * 68 + k + lr]);
            a[i][1] = __float_as_uint(sA[(row + 8) * 68 + k + lr]);
            a[i][2] = __float_as_uint(sA[row * 68 + k + 4 + lr]);
            a[i][3] = __float_as_uint(sA[(row + 8) * 68 + k + 4 + lr]);
        }
        #pragma unroll
        for (int j = 0; j < 8; j++) {
            int n0 = nc * 64 + 8 * j;
            int cs = (n0 + lq) ^ (lr << 3);
            uint32_t b0 = __float_as_uint(sW[(k + lr) * 256 + cs]);
            uint32_t b1 = __float_as_uint(sW[(k + 4 + lr) * 256 + cs]);
            mma_tf32(acc[0][j], a[0], b0, b1);
            mma_tf32(acc[1][j], a[1], b0, b1);
        }
    }

    #pragma unroll
    for (int i = 0; i < 2; i++) {
        int r0 = mh * 32 + 16 * i + lq;
        int g0 = n0g + r0, g1 = g0 + 8;
        #pragma unroll
        for (int j = 0; j < 8; j++) {
            int col = nc * 64 + 8 * j + 2 * lr;
            if (g0 < NN)
                *(float2*)&g_Pcat[(size_t)g0 * 256 + col] =
                    make_float2(acc[i][j][0], acc[i][j][1]);
            if (g1 < NN)
                *(float2*)&g_Pcat[(size_t)g1 * 256 + col] =
                    make_float2(acc[i][j][2], acc[i][j][3]);
        }
    }
}

// ---------------------------------------------------------------------------
// Edge kernel (R5 structure): 64-edge tiles, 256 threads, 2 CTAs/SM,
// next-tile reg prefetch of idx/ea. NEW: scatter via lane-paired red.v4.
// ---------------------------------------------------------------------------
__global__ __launch_bounds__(256, 2)
void edge_kernel(const int* __restrict__ ei,
                 const float* __restrict__ ea,
                 const float* __restrict__ eW1, const float* __restrict__ eb1,
                 const float* __restrict__ eW2, const float* __restrict__ eb2)
{
    extern __shared__ float sm[];
    float* sWea = sm;                     // 8 x 128, col-swizzled
    float* sW2  = sWea + 8 * MH;          // 128 x 64, col-swizzled
    float* sEA  = sW2 + MH * HD;          // 64 x 12
    float* sH   = sEA + ET * 12;          // 64 x 132
    int*   sSrc = (int*)(sH + ET * MHP);  // 64
    int*   sDst = sSrc + ET;              // 64

    const int tid  = threadIdx.x;
    const int lane = tid & 31;
    const int w    = tid >> 5;
    const int lq   = lane >> 2;
    const int lr   = lane & 3;

    for (int i = tid; i < 8 * MH; i += 256) {
        int k = i >> 7, c = i & 127;
        sWea[k * MH + (c ^ ((k & 3) << 3))] = f2tf(eW1[(2 * HD + k) * MH + c]);
    }
    for (int i = tid; i < MH * HD; i += 256) {
        int r = i >> 6, n = i & 63;
        sW2[r * HD + (n ^ ((r & 3) << 3))] = f2tf(eW2[i]);
    }

    const int mh = w >> 2;   // 0..1 -> m32
    const int nq = w & 3;    // 0..3 -> n32 (phase1) / n16 (phase2)

    float2 b1p[4], b2p[2];
    #pragma unroll
    for (int j = 0; j < 4; j++) b1p[j] = *(const float2*)&eb1[nq * 32 + 8 * j + 2 * lr];
    #pragma unroll
    for (int j = 0; j < 2; j++) b2p[j] = *(const float2*)&eb2[nq * 16 + 8 * j + 2 * lr];

    const int numTiles = NE / ET;   // 12500

    // prefetch first tile
    int pS = 0, pD = 0;
    float2 pEA = make_float2(0.f, 0.f);
    int t = blockIdx.x;
    if (t < numTiles) {
        const int e0 = t * ET;
        if (tid < ET) { pS = ei[e0 + tid]; pD = ei[NE + e0 + tid]; }
        pEA = *(const float2*)&ea[(size_t)e0 * 8 + 2 * tid];
    }

    for (; t < numTiles; t += gridDim.x) {
        __syncthreads();

        if (tid < ET) {
            sSrc[tid] = min(max(pS, 0), NN - 1);
            sDst[tid] = min(max(pD, 0), NN - 1);
        }
        {
            int idx = 2 * tid;
            int r = idx >> 3, c = idx & 7;
            sEA[r * 12 + c]     = f2tf(pEA.x);
            sEA[r * 12 + c + 1] = f2tf(pEA.y);
        }
        __syncthreads();

        int tn = t + gridDim.x;
        if (tn < numTiles) {
            const int en = tn * ET;
            if (tid < ET) { pS = ei[en + tid]; pD = ei[NE + en + tid]; }
            pEA = *(const float2*)&ea[(size_t)en * 8 + 2 * tid];
        }

        // ---- phase 1: [64,8] @ [8,128] ----
        float c1[2][4][4];
        #pragma unroll
        for (int i = 0; i < 2; i++)
            #pragma unroll
            for (int j = 0; j < 4; j++)
                #pragma unroll
                for (int q = 0; q < 4; q++) c1[i][j][q] = 0.f;

        {
            uint32_t a[2][4];
            #pragma unroll
            for (int i = 0; i < 2; i++) {
                int row = mh * 32 + 16 * i + lq;
                a[i][0] = __float_as_uint(sEA[row * 12 + lr]);
                a[i][1] = __float_as_uint(sEA[(row + 8) * 12 + lr]);
                a[i][2] = __float_as_uint(sEA[row * 12 + 4 + lr]);
                a[i][3] = __float_as_uint(sEA[(row + 8) * 12 + 4 + lr]);
            }
            #pragma unroll
            for (int j = 0; j < 4; j++) {
                int n0 = nq * 32 + 8 * j;
                int cs = (n0 + lq) ^ (lr << 3);
                uint32_t b0 = __float_as_uint(sWea[lr * MH + cs]);
                uint32_t b1 = __float_as_uint(sWea[(4 + lr) * MH + cs]);
                mma_tf32(c1[0][j], a[0], b0, b1);
                mma_tf32(c1[1][j], a[1], b0, b1);
            }
        }

        // gathered Pcat + bias, relu -> sH
        #pragma unroll
        for (int i = 0; i < 2; i++) {
            int r0 = mh * 32 + 16 * i + lq;
            int r1 = r0 + 8;
            const float* ps0 = g_Pcat + (size_t)sSrc[r0] * 256;
            const float* pd0 = g_Pcat + (size_t)sDst[r0] * 256 + MH;
            const float* ps1 = g_Pcat + (size_t)sSrc[r1] * 256;
            const float* pd1 = g_Pcat + (size_t)sDst[r1] * 256 + MH;
            #pragma unroll
            for (int j = 0; j < 4; j++) {
                int col = nq * 32 + 8 * j + 2 * lr;
                float2 s0 = *(const float2*)&ps0[col];
                float2 d0 = *(const float2*)&pd0[col];
                float2 s1 = *(const float2*)&ps1[col];
                float2 d1 = *(const float2*)&pd1[col];
                uint2 v0, v1;
                v0.x = __float_as_uint(f2tf(fmaxf(c1[i][j][0] + s0.x + d0.x + b1p[j].x, 0.f)));
                v0.y = __float_as_uint(f2tf(fmaxf(c1[i][j][1] + s0.y + d0.y + b1p[j].y, 0.f)));
                v1.x = __float_as_uint(f2tf(fmaxf(c1[i][j][2] + s1.x + d1.x + b1p[j].x, 0.f)));
                v1.y = __float_as_uint(f2tf(fmaxf(c1[i][j][3] + s1.y + d1.y + b1p[j].y, 0.f)));
                *(uint2*)&sH[r0 * MHP + col] = v0;
                *(uint2*)&sH[r1 * MHP + col] = v1;
            }
        }
        __syncthreads();

        // ---- phase 2: [64,128] @ [128,64] ----
        float c2[2][2][4];
        #pragma unroll
        for (int i = 0; i < 2; i++)
            #pragma unroll
            for (int j = 0; j < 2; j++)
                #pragma unroll
                for (int q = 0; q < 4; q++) c2[i][j][q] = 0.f;

        for (int k = 0; k < MH; k += 8) {
            uint32_t a[2][4];
            #pragma unroll
            for (int i = 0; i < 2; i++) {
                int row = mh * 32 + 16 * i + lq;
                a[i][0] = __float_as_uint(sH[row * MHP + k + lr]);
                a[i][1] = __float_as_uint(sH[(row + 8) * MHP + k + lr]);
                a[i][2] = __float_as_uint(sH[row * MHP + k + 4 + lr]);
                a[i][3] = __float_as_uint(sH[(row + 8) * MHP + k + 4 + lr]);
            }
            #pragma unroll
            for (int j = 0; j < 2; j++) {
                int n0 = nq * 16 + 8 * j;
                int cs = (n0 + lq) ^ (lr << 3);
                uint32_t b0 = __float_as_uint(sW2[(k + lr) * HD + cs]);
                uint32_t b1 = __float_as_uint(sW2[(k + 4 + lr) * HD + cs]);
                mma_tf32(c2[0][j], a[0], b0, b1);
                mma_tf32(c2[1][j], a[1], b0, b1);
            }
        }

        // scatter-add: pair lanes (lr, lr^1) -> red.v4 from even-lr lanes
        #pragma unroll
        for (int i = 0; i < 2; i++) {
            int r0 = mh * 32 + 16 * i + lq;
            int r1 = r0 + 8;
            int d0 = sDst[r0], d1 = sDst[r1];
            #pragma unroll
            for (int j = 0; j < 2; j++) {
                float u0 = c2[i][j][0] + b2p[j].x;
                float u1 = c2[i][j][1] + b2p[j].y;
                float u2 = c2[i][j][2] + b2p[j].x;
                float u3 = c2[i][j][3] + b2p[j].y;
                float w0 = __shfl_xor_sync(0xffffffffu, u0, 1);
                float w1 = __shfl_xor_sync(0xffffffffu, u1, 1);
                float w2 = __shfl_xor_sync(0xffffffffu, u2, 1);
                float w3 = __shfl_xor_sync(0xffffffffu, u3, 1);
                if (!(lr & 1)) {
                    int col = nq * 16 + 8 * j + (lr & 2) * 2;  // lr=0 -> +0, lr=2 -> +4
                    float* p0 = g_agg + (size_t)d0 * HD + col;
                    float* p1 = g_agg + (size_t)d1 * HD + col;
                    asm volatile("red.global.add.v4.f32 [%0], {%1, %2, %3, %4};"
                                 :: "l"(p0), "f"(u0), "f"(u1), "f"(w0), "f"(w1)
                                 : "memory");
                    asm volatile("red.global.add.v4.f32 [%0], {%1, %2, %3, %4};"
                                 :: "l"(p1), "f"(u2), "f"(u3), "f"(w2), "f"(w3)
                                 : "memory");
                }
            }
        }
    }
}

// ---------------------------------------------------------------------------
// Node kernel: tf32 MMA, 64 nodes/tile, 256 threads.
// NEW: next-tile register prefetch of the [h | agg] gather.
// ---------------------------------------------------------------------------
#define TILE 64
__global__ __launch_bounds__(256, 1)
void node_kernel(const float* __restrict__ h,
                 const float* __restrict__ nW1, const float* __restrict__ nb1,
                 const float* __restrict__ nW2, const float* __restrict__ nb2,
                 const float* __restrict__ lg,  const float* __restrict__ lb,
                 float* __restrict__ out)
{
    extern __shared__ float sm[];
    float* sW1 = sm;
    float* sW2 = sW1 + MH * MH;
    float* sU  = sW2 + MH * HD;
    float* sH  = sU  + TILE * MHP;
    float* sO  = sH  + TILE * MHP;
    float* sB1 = sO  + TILE * 65;
    float* sB2 = sB1 + MH;
    float* sG  = sB2 + HD;
    float* sB  = sG  + HD;
    float* sMu = sB  + HD;
    float* sRs = sMu + TILE;

    const int tid  = threadIdx.x;
    const int lane = tid & 31;
    const int w    = tid >> 5;
    const int lq   = lane >> 2;
    const int lr   = lane & 3;

    for (int i = tid; i < MH * MH; i += 256) {
        int r = i >> 7, n = i & 127;
        sW1[r * MH + (n ^ ((r & 3) << 3))] = f2tf(nW1[i]);
    }
    for (int i = tid; i < MH * HD; i += 256) {
        int r = i >> 6, n = i & 63;
        sW2[r * HD + (n ^ ((r & 3) << 3))] = f2tf(nW2[i]);
    }
    for (int i = tid; i < MH; i += 256) sB1[i] = nb1[i];
    if (tid < HD) { sB2[tid] = nb2[tid]; sG[tid] = lg[tid]; sB[tid] = lb[tid]; }
    __syncthreads();

    const int mh = w >> 2, nq = w & 3;
    const int mq = w & 3,  nh = w >> 2;

    float2 b1p[4], b2p[4];
    #pragma unroll
    for (int j = 0; j < 4; j++) {
        b1p[j] = *(const float2*)&sB1[nq * 32 + 8 * j + 2 * lr];
        b2p[j] = *(const float2*)&sB2[nh * 32 + 8 * j + 2 * lr];
    }

    const int numTiles = (NN + TILE - 1) / TILE;

    // prefetch first tile's [h | agg] gather into registers
    float pf[32];
    int t = blockIdx.x;
    if (t < numTiles) {
        const int n0g = t * TILE;
        #pragma unroll
        for (int v = 0; v < 32; v++) {
            int i = v * 256 + tid;
            int r = i >> 7, k = i & 127;
            int node = min(n0g + r, NN - 1);
            pf[v] = (k < HD) ? h[(size_t)node * HD + k]
                             : g_agg[(size_t)node * HD + (k - HD)];
        }
    }

    for (; t < numTiles; t += gridDim.x) {
        const int n0g = t * TILE;
        __syncthreads();

        // commit prefetched gather -> sU
        #pragma unroll
        for (int v = 0; v < 32; v++) {
            int i = v * 256 + tid;
            int r = i >> 7, k = i & 127;
            sU[r * MHP + k] = f2tf(pf[v]);
        }
        __syncthreads();

        // issue next tile's gather (hidden under this tile's compute)
        int tn = t + gridDim.x;
        if (tn < numTiles) {
            const int nn0 = tn * TILE;
            #pragma unroll
            for (int v = 0; v < 32; v++) {
                int i = v * 256 + tid;
                int r = i >> 7, k = i & 127;
                int node = min(nn0 + r, NN - 1);
                pf[v] = (k < HD) ? h[(size_t)node * HD + k]
                                 : g_agg[(size_t)node * HD + (k - HD)];
            }
        }

        float c1[2][4][4];
        #pragma unroll
        for (int i = 0; i < 2; i++)
            #pragma unroll
            for (int j = 0; j < 4; j++)
                #pragma unroll
                for (int q = 0; q < 4; q++) c1[i][j][q] = 0.f;

        for (int k = 0; k < MH; k += 8) {
            uint32_t a[2][4];
            #pragma unroll
            for (int i = 0; i < 2; i++) {
                int row = mh * 32 + 16 * i + lq;
                a[i][0] = __float_as_uint(sU[row * MHP + k + lr]);
                a[i][1] = __float_as_uint(sU[(row + 8) * MHP + k + lr]);
                a[i][2] = __float_as_uint(sU[row * MHP + k + 4 + lr]);
                a[i][3] = __float_as_uint(sU[(row + 8) * MHP + k + 4 + lr]);
            }
            #pragma unroll
            for (int j = 0; j < 4; j++) {
                int n0 = nq * 32 + 8 * j;
                int cs = (n0 + lq) ^ (lr << 3);
                uint32_t b0 = __float_as_uint(sW1[(k + lr) * MH + cs]);
                uint32_t b1 = __float_as_uint(sW1[(k + 4 + lr) * MH + cs]);
                mma_tf32(c1[0][j], a[0], b0, b1);
                mma_tf32(c1[1][j], a[1], b0, b1);
            }
        }

        #pragma unroll
        for (int i = 0; i < 2; i++) {
            #pragma unroll
            for (int j = 0; j < 4; j++) {
                int row = mh * 32 + 16 * i + lq;
                int col = nq * 32 + 8 * j + 2 * lr;
                uint2 v0, v1;
                v0.x = __float_as_uint(f2tf(fmaxf(c1[i][j][0] + b1p[j].x, 0.f)));
                v0.y = __float_as_uint(f2tf(fmaxf(c1[i][j][1] + b1p[j].y, 0.f)));
                v1.x = __float_as_uint(f2tf(fmaxf(c1[i][j][2] + b1p[j].x, 0.f)));
                v1.y = __float_as_uint(f2tf(fmaxf(c1[i][j][3] + b1p[j].y, 0.f)));
                *(uint2*)&sH[row * MHP + col]       = v0;
                *(uint2*)&sH[(row + 8) * MHP + col] = v1;
            }
        }
        __syncthreads();

        float c2[4][4];
        #pragma unroll
        for (int j = 0; j < 4; j++)
            #pragma unroll
            for (int q = 0; q < 4; q++) c2[j][q] = 0.f;

        const int m0 = mq * 16;
        for (int k = 0; k < MH; k += 8) {
            uint32_t a[4];
            int row = m0 + lq;
            a[0] = __float_as_uint(sH[row * MHP + k + lr]);
            a[1] = __float_as_uint(sH[(row + 8) * MHP + k + lr]);
            a[2] = __float_as_uint(sH[row * MHP + k + 4 + lr]);
            a[3] = __float_as_uint(sH[(row + 8) * MHP + k + 4 + lr]);
            #pragma unroll
            for (int j = 0; j < 4; j++) {
                int n0 = nh * 32 + 8 * j;
                int cs = (n0 + lq) ^ (lr << 3);
                uint32_t b0 = __float_as_uint(sW2[(k + lr) * HD + cs]);
                uint32_t b1 = __float_as_uint(sW2[(k + 4 + lr) * HD + cs]);
                mma_tf32(c2[j], a, b0, b1);
            }
        }

        {
            int r0 = m0 + lq;
            int r1 = r0 + 8;
            int g0 = n0g + r0, g1 = n0g + r1;
            #pragma unroll
            for (int j = 0; j < 4; j++) {
                int col = nh * 32 + 8 * j + 2 * lr;
                if (g0 < NN) {
                    float2 hv = *(const float2*)&h[(size_t)g0 * HD + col];
                    sO[r0 * 65 + col]     = c2[j][0] + b2p[j].x + hv.x;
                    sO[r0 * 65 + col + 1] = c2[j][1] + b2p[j].y + hv.y;
                }
                if (g1 < NN) {
                    float2 hv = *(const float2*)&h[(size_t)g1 * HD + col];
                    sO[r1 * 65 + col]     = c2[j][2] + b2p[j].x + hv.x;
                    sO[r1 * 65 + col + 1] = c2[j][3] + b2p[j].y + hv.y;
                }
            }
        }
        __syncthreads();

        if (tid < TILE) {
            float s = 0.f, s2 = 0.f;
            #pragma unroll 8
            for (int c = 0; c < HD; c++) {
                float v = sO[tid * 65 + c];
                s += v;
                s2 = fmaf(v, v, s2);
            }
            float mu  = s * (1.f / HD);
            float var = fmaxf(s2 * (1.f / HD) - mu * mu, 0.f);
            sMu[tid] = mu;
            sRs[tid] = rsqrtf(var + 1e-5f);
        }
        __syncthreads();

        for (int i = tid; i < TILE * HD; i += 256) {
            int r = i >> 6;
            int c = i & 63;
            int node = n0g + r;
            if (node < NN)
                out[(size_t)node * HD + c] =
                    (sO[r * 65 + c] - sMu[r]) * sRs[r] * sG[c] + sB[c];
        }
    }
}

// ---------------------------------------------------------------------------
extern "C" void kernel_launch(void* const* d_in, const int* in_sizes, int n_in,
                              void* d_out, int out_size)
{
    const float* h   = (const float*)d_in[0];
    const int*   ei  = (const int*)d_in[1];     // int32 (JAX default downcast)
    const float* ea  = (const float*)d_in[2];
    const float* eW1 = (const float*)d_in[3];
    const float* eb1 = (const float*)d_in[4];
    const float* eW2 = (const float*)d_in[5];
    const float* eb2 = (const float*)d_in[6];
    const float* nW1 = (const float*)d_in[7];
    const float* nb1 = (const float*)d_in[8];
    const float* nW2 = (const float*)d_in[9];
    const float* nb2 = (const float*)d_in[10];
    const float* lg  = (const float*)d_in[11];
    const float* lb  = (const float*)d_in[12];
    float*       out = (float*)d_out;

    const int smem_prep = (64 * 256 + 128 * 68) * 4;
    const int smem_edge = (8 * MH + MH * HD + ET * 12 + ET * MHP) * 4
                          + 2 * ET * 4;
    const int smem_node = (MH * MH + MH * HD + 2 * TILE * MHP + TILE * 65
                           + MH + 5 * HD + TILE) * 4;

    cudaFuncSetAttribute(prep_kernel, cudaFuncAttributeMaxDynamicSharedMemorySize, smem_prep);
    cudaFuncSetAttribute(edge_kernel, cudaFuncAttributeMaxDynamicSharedMemorySize, smem_edge);
    cudaFuncSetAttribute(node_kernel, cudaFuncAttributeMaxDynamicSharedMemorySize, smem_node);

    prep_kernel<<<(NN + 127) / 128, 512, smem_prep>>>(h, eW1);
    edge_kernel<<<296, 256, smem_edge>>>(ei, ea, eW1, eb1, eW2, eb2);
    node_kernel<<<148, 256, smem_node>>>(h, nW1, nb1, nW2, nb2, lg, lb, out);
}